// round 1
// baseline (speedup 1.0000x reference)
#include <cuda_runtime.h>
#include <cuda_bf16.h>
#include <cstdint>
#include <cstddef>

// Problem constants
#define S_LEN 2048
#define E_DIM 4096
#define H_NUM 16
#define D_DIM 256
#define RD_DIM 64

// Scratch (device globals -- allocation inside kernel_launch is forbidden)
__device__ float g_Q[(size_t)S_LEN * E_DIM];
__device__ float g_K[(size_t)S_LEN * E_DIM];
__device__ float g_V[(size_t)S_LEN * E_DIM];
__device__ float g_ATT[(size_t)S_LEN * E_DIM];
__device__ float g_P[(size_t)H_NUM * S_LEN * S_LEN];   // 268 MB score/prob scratch

// ---------------------------------------------------------------------------
// 3xTF32 helpers
// ---------------------------------------------------------------------------
__device__ __forceinline__ void split_tf32(float x, uint32_t& hi, uint32_t& lo) {
    uint32_t h;
    asm("cvt.rna.tf32.f32 %0, %1;" : "=r"(h) : "f"(x));
    float r = x - __uint_as_float(h);
    asm("cvt.rna.tf32.f32 %0, %1;" : "=r"(lo) : "f"(r));
    hi = h;
}

__device__ __forceinline__ void mma8(float c[4], const uint32_t a[4], const uint32_t b[2]) {
    asm volatile(
        "mma.sync.aligned.m16n8k8.row.col.f32.tf32.tf32.f32 "
        "{%0,%1,%2,%3},{%4,%5,%6,%7},{%8,%9},{%0,%1,%2,%3};\n"
        : "+f"(c[0]), "+f"(c[1]), "+f"(c[2]), "+f"(c[3])
        : "r"(a[0]), "r"(a[1]), "r"(a[2]), "r"(a[3]), "r"(b[0]), "r"(b[1]));
}

// ---------------------------------------------------------------------------
// Generic 128x128x32 GEMM, C = alpha * A @ B (optionally B given as N x K).
// Batched over blockIdx.z via element strides. M, N implied by grid.
// SKIP_UPPER: skip CTAs strictly above the causal diagonal (scores).
// KLIMIT: clamp K loop at (blockIdx.y + 1) * 128 (causal P @ V).
// ---------------------------------------------------------------------------
#define BM 128
#define BN 128
#define BK 32

template<bool BTRANS, bool SKIP_UPPER, bool KLIMIT>
__global__ void __launch_bounds__(256, 1)
gemm_tf32x3(const float* __restrict__ A, int lda, size_t sA,
            const float* __restrict__ B, int ldb, size_t sB,
            float* __restrict__ C, int ldc, size_t sC,
            int K, float alpha)
{
    if (SKIP_UPPER && blockIdx.x > blockIdx.y) return;
    A += (size_t)blockIdx.z * sA;
    B += (size_t)blockIdx.z * sB;
    C += (size_t)blockIdx.z * sC;

    const int bm = blockIdx.y * BM;
    const int bn = blockIdx.x * BN;
    const int Keff = KLIMIT ? min(K, (int)(blockIdx.y + 1) * BM) : K;

    __shared__ float As[BM][BK + 4];   // +4 pad: conflict-free frag reads, 16B-aligned rows
    __shared__ float Bs[BK][BN + 4];

    const int tid  = threadIdx.x;
    const int lane = tid & 31;
    const int warp = tid >> 5;
    const int wm   = (warp >> 2) * 64;   // warp m-offset (2 warps in m)
    const int wn   = (warp & 3) * 32;    // warp n-offset (4 warps in n)
    const int lr   = lane >> 2;          // group id 0..7
    const int lc   = lane & 3;           // thread-in-group 0..3

    float acc[4][4][4];
#pragma unroll
    for (int i = 0; i < 4; i++)
#pragma unroll
        for (int j = 0; j < 4; j++)
#pragma unroll
            for (int r = 0; r < 4; r++) acc[i][j][r] = 0.f;

    for (int k0 = 0; k0 < Keff; k0 += BK) {
        // --- load A tile (128 x 32), vectorized along K ---
#pragma unroll
        for (int i = 0; i < 4; i++) {
            int lin = tid + i * 256;
            int row = lin >> 3;
            int c4  = (lin & 7) * 4;
            float4 v = *reinterpret_cast<const float4*>(A + (size_t)(bm + row) * lda + k0 + c4);
            *reinterpret_cast<float4*>(&As[row][c4]) = v;
        }
        // --- load B tile into Bs[k][n] ---
        if (!BTRANS) {
#pragma unroll
            for (int i = 0; i < 4; i++) {
                int lin = tid + i * 256;
                int kk = lin >> 5;
                int c4 = (lin & 31) * 4;
                float4 v = *reinterpret_cast<const float4*>(B + (size_t)(k0 + kk) * ldb + bn + c4);
                *reinterpret_cast<float4*>(&Bs[kk][c4]) = v;
            }
        } else {
            // B stored as N x K (row n contiguous in k): transpose into Bs
#pragma unroll
            for (int i = 0; i < 4; i++) {
                int lin = tid + i * 256;
                int n  = lin >> 3;
                int c4 = (lin & 7) * 4;
                float4 v = *reinterpret_cast<const float4*>(B + (size_t)(bn + n) * ldb + k0 + c4);
                Bs[c4 + 0][n] = v.x;
                Bs[c4 + 1][n] = v.y;
                Bs[c4 + 2][n] = v.z;
                Bs[c4 + 3][n] = v.w;
            }
        }
        __syncthreads();

#pragma unroll
        for (int ks = 0; ks < BK; ks += 8) {
            uint32_t ah[4][4], al[4][4], bh[4][2], bl[4][2];
#pragma unroll
            for (int mt = 0; mt < 4; mt++) {
                int r0 = wm + mt * 16 + lr;
                split_tf32(As[r0][ks + lc],         ah[mt][0], al[mt][0]);
                split_tf32(As[r0 + 8][ks + lc],     ah[mt][1], al[mt][1]);
                split_tf32(As[r0][ks + lc + 4],     ah[mt][2], al[mt][2]);
                split_tf32(As[r0 + 8][ks + lc + 4], ah[mt][3], al[mt][3]);
            }
#pragma unroll
            for (int nt = 0; nt < 4; nt++) {
                int n = wn + nt * 8 + lr;
                split_tf32(Bs[ks + lc][n],     bh[nt][0], bl[nt][0]);
                split_tf32(Bs[ks + lc + 4][n], bh[nt][1], bl[nt][1]);
            }
#pragma unroll
            for (int mt = 0; mt < 4; mt++)
#pragma unroll
                for (int nt = 0; nt < 4; nt++) {
                    mma8(acc[mt][nt], ah[mt], bh[nt]);   // hi*hi
                    mma8(acc[mt][nt], ah[mt], bl[nt]);   // hi*lo
                    mma8(acc[mt][nt], al[mt], bh[nt]);   // lo*hi
                }
        }
        __syncthreads();
    }

    // --- epilogue ---
#pragma unroll
    for (int mt = 0; mt < 4; mt++)
#pragma unroll
        for (int nt = 0; nt < 4; nt++) {
            int r0 = bm + wm + mt * 16 + lr;
            int c0 = bn + wn + nt * 8 + lc * 2;
            C[(size_t)r0 * ldc + c0]           = acc[mt][nt][0] * alpha;
            C[(size_t)r0 * ldc + c0 + 1]       = acc[mt][nt][1] * alpha;
            C[(size_t)(r0 + 8) * ldc + c0]     = acc[mt][nt][2] * alpha;
            C[(size_t)(r0 + 8) * ldc + c0 + 1] = acc[mt][nt][3] * alpha;
        }
}

// ---------------------------------------------------------------------------
// RoPE on first RD dims of every head of Q and K (GPT-J rotate_every_two)
// ---------------------------------------------------------------------------
__global__ void rope_kernel(float* __restrict__ Q, float* __restrict__ Km,
                            const int* __restrict__ pos)
{
    const int s = blockIdx.x;
    const float p = (float)pos[s];
    for (int idx = threadIdx.x; idx < H_NUM * (RD_DIM / 2); idx += blockDim.x) {
        int h = idx >> 5;          // RD/2 = 32 pairs per head
        int j = idx & 31;
        float inv = (float)pow(10000.0, -(double)(2 * j) / (double)RD_DIM);
        float ang = p * inv;
        float sn, cs;
        sincosf(ang, &sn, &cs);
        size_t base = (size_t)s * E_DIM + (size_t)h * D_DIM + 2 * j;
        float q0 = Q[base], q1 = Q[base + 1];
        Q[base]     = q0 * cs - q1 * sn;
        Q[base + 1] = q1 * cs + q0 * sn;
        float k0 = Km[base], k1 = Km[base + 1];
        Km[base]     = k0 * cs - k1 * sn;
        Km[base + 1] = k1 * cs + k0 * sn;
    }
}

// ---------------------------------------------------------------------------
// Causal softmax over one row; zero-fills the masked upper triangle.
// grid: (S, H), 256 threads
// ---------------------------------------------------------------------------
__global__ void softmax_causal(float* __restrict__ P)
{
    const int m = blockIdx.x, h = blockIdx.y, tid = threadIdx.x;
    float* row = P + ((size_t)h * S_LEN + m) * S_LEN;
    const int nv = m + 1;
    __shared__ float sh[8];

    float mx = -3.4e38f;
    for (int n = tid; n < nv; n += 256) mx = fmaxf(mx, row[n]);
#pragma unroll
    for (int o = 16; o; o >>= 1) mx = fmaxf(mx, __shfl_xor_sync(0xffffffffu, mx, o));
    if ((tid & 31) == 0) sh[tid >> 5] = mx;
    __syncthreads();
    float bmax = sh[0];
#pragma unroll
    for (int w = 1; w < 8; w++) bmax = fmaxf(bmax, sh[w]);
    __syncthreads();

    float s = 0.f;
    for (int n = tid; n < nv; n += 256) {
        float e = __expf(row[n] - bmax);
        row[n] = e;
        s += e;
    }
#pragma unroll
    for (int o = 16; o; o >>= 1) s += __shfl_xor_sync(0xffffffffu, s, o);
    if ((tid & 31) == 0) sh[tid >> 5] = s;
    __syncthreads();
    float tot = 0.f;
#pragma unroll
    for (int w = 0; w < 8; w++) tot += sh[w];
    float inv = 1.f / tot;

    for (int n = tid; n < S_LEN; n += 256)
        row[n] = (n < nv) ? row[n] * inv : 0.f;
}

// ---------------------------------------------------------------------------
// Launch
// ---------------------------------------------------------------------------
extern "C" void kernel_launch(void* const* d_in, const int* in_sizes, int n_in,
                              void* d_out, int out_size)
{
    const float* hidden = (const float*)d_in[0];
    const float* wq     = (const float*)d_in[1];
    const float* wk     = (const float*)d_in[2];
    const float* wv     = (const float*)d_in[3];
    const float* wo     = (const float*)d_in[4];
    const int*   pos    = (const int*)d_in[5];
    float* out = (float*)d_out;

    float *Q, *K, *V, *ATT, *P;
    cudaGetSymbolAddress((void**)&Q,   g_Q);
    cudaGetSymbolAddress((void**)&K,   g_K);
    cudaGetSymbolAddress((void**)&V,   g_V);
    cudaGetSymbolAddress((void**)&ATT, g_ATT);
    cudaGetSymbolAddress((void**)&P,   g_P);

    dim3 blk(256);

    // 1) Q/K/V projections: (2048 x 4096) @ (4096 x 4096)
    dim3 gproj(E_DIM / BN, S_LEN / BM, 1);
    gemm_tf32x3<false, false, false><<<gproj, blk>>>(hidden, E_DIM, 0, wq, E_DIM, 0, Q, E_DIM, 0, E_DIM, 1.f);
    gemm_tf32x3<false, false, false><<<gproj, blk>>>(hidden, E_DIM, 0, wk, E_DIM, 0, K, E_DIM, 0, E_DIM, 1.f);
    gemm_tf32x3<false, false, false><<<gproj, blk>>>(hidden, E_DIM, 0, wv, E_DIM, 0, V, E_DIM, 0, E_DIM, 1.f);

    // 2) RoPE on Q, K
    rope_kernel<<<S_LEN, 256>>>(Q, K, pos);

    // 3) scores[h] = (Q_h @ K_h^T) / sqrt(D), upper-tri blocks skipped
    dim3 gsc(S_LEN / BN, S_LEN / BM, H_NUM);
    gemm_tf32x3<true, true, false><<<gsc, blk>>>(
        Q, E_DIM, (size_t)D_DIM,
        K, E_DIM, (size_t)D_DIM,
        P, S_LEN, (size_t)S_LEN * S_LEN,
        D_DIM, 0.0625f);

    // 4) causal softmax (zero-fills masked region)
    softmax_causal<<<dim3(S_LEN, H_NUM), 256>>>(P);

    // 5) attn[h] = P_h @ V_h  (K loop clamped causally)
    dim3 gav(D_DIM / BN, S_LEN / BM, H_NUM);
    gemm_tf32x3<false, false, true><<<gav, blk>>>(
        P, S_LEN, (size_t)S_LEN * S_LEN,
        V, E_DIM, (size_t)D_DIM,
        ATT, E_DIM, (size_t)D_DIM,
        S_LEN, 1.f);

    // 6) out = attn @ wo
    gemm_tf32x3<false, false, false><<<gproj, blk>>>(ATT, E_DIM, 0, wo, E_DIM, 0, out, E_DIM, 0, E_DIM, 1.f);
}

// round 2
// speedup vs baseline: 2.2771x; 2.2771x over previous
#include <cuda_runtime.h>
#include <cuda_bf16.h>
#include <cstdint>
#include <cstddef>

#define S_LEN 2048
#define E_DIM 4096
#define H_NUM 16
#define D_DIM 256
#define RD_DIM 64

// Scratch (device globals -- allocation inside kernel_launch is forbidden)
__device__ float g_Q[(size_t)S_LEN * E_DIM];
__device__ float g_K[(size_t)S_LEN * E_DIM];
__device__ float g_V[(size_t)S_LEN * E_DIM];
__device__ float g_ATT[(size_t)S_LEN * E_DIM];
__device__ float g_P[(size_t)H_NUM * S_LEN * S_LEN];

// ---------------------------------------------------------------------------
// bf16 split helpers: x = hi + lo, each bf16. Packs (x,y) pairs into one u32.
// ---------------------------------------------------------------------------
__device__ __forceinline__ uint32_t pack_split(float x, float y, uint32_t& lo) {
    __nv_bfloat162 h = __floats2bfloat162_rn(x, y);
    float rx = x - __bfloat162float(h.x);
    float ry = y - __bfloat162float(h.y);
    __nv_bfloat162 l = __floats2bfloat162_rn(rx, ry);
    lo = *reinterpret_cast<uint32_t*>(&l);
    return *reinterpret_cast<uint32_t*>(&h);
}

__device__ __forceinline__ void mma16(float c[4], const uint32_t a[4], const uint32_t b[2]) {
    asm volatile(
        "mma.sync.aligned.m16n8k16.row.col.f32.bf16.bf16.f32 "
        "{%0,%1,%2,%3},{%4,%5,%6,%7},{%8,%9},{%0,%1,%2,%3};\n"
        : "+f"(c[0]), "+f"(c[1]), "+f"(c[2]), "+f"(c[3])
        : "r"(a[0]), "r"(a[1]), "r"(a[2]), "r"(a[3]), "r"(b[0]), "r"(b[1]));
}

// ---------------------------------------------------------------------------
// 128x128x32 GEMM, C = alpha * A @ B, 3xBF16 emulation (hh + hl + lh).
// smem holds pre-split hi/lo bf16 pairs in fragment order; double-buffered.
// ---------------------------------------------------------------------------
#define BM 128
#define BN 128
#define BK 32
#define A_STR 20     // uint32 stride per A row (16 pairs + pad 4): conflict-free LDS
#define B_STR 136    // uint32 stride per B k2-row (128 + pad 8): conflict-free LDS
#define A_WORDS (128 * A_STR)
#define B_WORDS (16 * B_STR)
#define STG_WORDS (2 * A_WORDS + 2 * B_WORDS)   // AH, AL, BH, BL
#define SMEM_BYTES (2 * STG_WORDS * 4)

template<bool BTRANS, bool SKIP_UPPER, bool KLIMIT>
__global__ void __launch_bounds__(256, 1)
gemm_bf16x3(const float* __restrict__ A, int lda, size_t sA,
            const float* __restrict__ B, int ldb, size_t sB,
            float* __restrict__ C, int ldc, size_t sC,
            int K, float alpha)
{
    if (SKIP_UPPER && blockIdx.x > blockIdx.y) return;
    A += (size_t)blockIdx.z * sA;
    B += (size_t)blockIdx.z * sB;
    C += (size_t)blockIdx.z * sC;

    const int bm = blockIdx.y * BM;
    const int bn = blockIdx.x * BN;
    const int Keff = KLIMIT ? min(K, (int)(blockIdx.y + 1) * BM) : K;
    const int niter = Keff >> 5;

    extern __shared__ uint32_t sm[];

    const int tid  = threadIdx.x;
    const int lane = tid & 31;
    const int warp = tid >> 5;
    const int wm   = (warp >> 2) * 64;
    const int wn   = (warp & 3) * 32;
    const int lr   = lane >> 2;
    const int lc   = lane & 3;

    float acc[4][4][4];
#pragma unroll
    for (int i = 0; i < 4; i++)
#pragma unroll
        for (int j = 0; j < 4; j++)
#pragma unroll
            for (int r = 0; r < 4; r++) acc[i][j][r] = 0.f;

    float4 ra[4], rb[4];

    // ---- loaders (global -> regs) ----
    auto load_tiles = [&](int k0) {
#pragma unroll
        for (int i = 0; i < 4; i++) {
            int lin = tid + i * 256;
            int row = lin >> 3;
            int c4  = (lin & 7) * 4;
            ra[i] = *reinterpret_cast<const float4*>(A + (size_t)(bm + row) * lda + k0 + c4);
        }
        if (BTRANS) {
#pragma unroll
            for (int i = 0; i < 4; i++) {
                int lin = tid + i * 256;
                int n  = lin >> 3;
                int c4 = (lin & 7) * 4;
                rb[i] = *reinterpret_cast<const float4*>(B + (size_t)(bn + n) * ldb + k0 + c4);
            }
        } else {
#pragma unroll
            for (int i = 0; i < 2; i++) {
                int lin = tid + i * 256;
                int k2 = lin >> 5;
                int n0 = (lin & 31) * 4;
                rb[2 * i]     = *reinterpret_cast<const float4*>(B + (size_t)(k0 + 2 * k2)     * ldb + bn + n0);
                rb[2 * i + 1] = *reinterpret_cast<const float4*>(B + (size_t)(k0 + 2 * k2 + 1) * ldb + bn + n0);
            }
        }
    };

    // ---- split + store (regs -> smem stage) ----
    auto store_tiles = [&](int st) {
        uint32_t* AH = sm + st * STG_WORDS;
        uint32_t* AL = AH + A_WORDS;
        uint32_t* BH = AL + A_WORDS;
        uint32_t* BL = BH + B_WORDS;
#pragma unroll
        for (int i = 0; i < 4; i++) {
            int lin = tid + i * 256;
            int row = lin >> 3;
            int k2  = (lin & 7) * 2;
            uint32_t lo0, lo1;
            uint32_t hi0 = pack_split(ra[i].x, ra[i].y, lo0);
            uint32_t hi1 = pack_split(ra[i].z, ra[i].w, lo1);
            AH[row * A_STR + k2]     = hi0;
            AH[row * A_STR + k2 + 1] = hi1;
            AL[row * A_STR + k2]     = lo0;
            AL[row * A_STR + k2 + 1] = lo1;
        }
        if (BTRANS) {
#pragma unroll
            for (int i = 0; i < 4; i++) {
                int lin = tid + i * 256;
                int n  = lin >> 3;
                int k2 = (lin & 7) * 2;
                uint32_t lo0, lo1;
                uint32_t hi0 = pack_split(rb[i].x, rb[i].y, lo0);
                uint32_t hi1 = pack_split(rb[i].z, rb[i].w, lo1);
                BH[k2 * B_STR + n]       = hi0;
                BH[(k2 + 1) * B_STR + n] = hi1;
                BL[k2 * B_STR + n]       = lo0;
                BL[(k2 + 1) * B_STR + n] = lo1;
            }
        } else {
#pragma unroll
            for (int i = 0; i < 2; i++) {
                int lin = tid + i * 256;
                int k2 = lin >> 5;
                int n0 = (lin & 31) * 4;
                const float* f0 = reinterpret_cast<const float*>(&rb[2 * i]);
                const float* f1 = reinterpret_cast<const float*>(&rb[2 * i + 1]);
#pragma unroll
                for (int j = 0; j < 4; j++) {
                    uint32_t lo;
                    uint32_t hi = pack_split(f0[j], f1[j], lo);
                    BH[k2 * B_STR + n0 + j] = hi;
                    BL[k2 * B_STR + n0 + j] = lo;
                }
            }
        }
    };

    // ---- pipeline ----
    load_tiles(0);
    store_tiles(0);
    __syncthreads();

    for (int it = 0; it < niter; ++it) {
        if (it + 1 < niter) load_tiles((it + 1) << 5);

        const int st = it & 1;
        const uint32_t* AH = sm + st * STG_WORDS;
        const uint32_t* AL = AH + A_WORDS;
        const uint32_t* BH = AL + A_WORDS;
        const uint32_t* BL = BH + B_WORDS;

#pragma unroll
        for (int ks2 = 0; ks2 < 16; ks2 += 8) {
            uint32_t ah[4][4], al[4][4], bh[4][2], bl[4][2];
#pragma unroll
            for (int mt = 0; mt < 4; mt++) {
                int r0 = wm + mt * 16 + lr;
                ah[mt][0] = AH[r0 * A_STR + ks2 + lc];
                ah[mt][1] = AH[(r0 + 8) * A_STR + ks2 + lc];
                ah[mt][2] = AH[r0 * A_STR + ks2 + lc + 4];
                ah[mt][3] = AH[(r0 + 8) * A_STR + ks2 + lc + 4];
                al[mt][0] = AL[r0 * A_STR + ks2 + lc];
                al[mt][1] = AL[(r0 + 8) * A_STR + ks2 + lc];
                al[mt][2] = AL[r0 * A_STR + ks2 + lc + 4];
                al[mt][3] = AL[(r0 + 8) * A_STR + ks2 + lc + 4];
            }
#pragma unroll
            for (int nt = 0; nt < 4; nt++) {
                int n = wn + nt * 8 + lr;
                bh[nt][0] = BH[(ks2 + lc) * B_STR + n];
                bh[nt][1] = BH[(ks2 + lc + 4) * B_STR + n];
                bl[nt][0] = BL[(ks2 + lc) * B_STR + n];
                bl[nt][1] = BL[(ks2 + lc + 4) * B_STR + n];
            }
#pragma unroll
            for (int mt = 0; mt < 4; mt++)
#pragma unroll
                for (int nt = 0; nt < 4; nt++) {
                    mma16(acc[mt][nt], ah[mt], bh[nt]);   // hi*hi
                    mma16(acc[mt][nt], ah[mt], bl[nt]);   // hi*lo
                    mma16(acc[mt][nt], al[mt], bh[nt]);   // lo*hi
                }
        }

        if (it + 1 < niter) store_tiles((it + 1) & 1);
        __syncthreads();
    }

    // ---- epilogue ----
#pragma unroll
    for (int mt = 0; mt < 4; mt++)
#pragma unroll
        for (int nt = 0; nt < 4; nt++) {
            int r0 = bm + wm + mt * 16 + lr;
            int c0 = bn + wn + nt * 8 + lc * 2;
            C[(size_t)r0 * ldc + c0]           = acc[mt][nt][0] * alpha;
            C[(size_t)r0 * ldc + c0 + 1]       = acc[mt][nt][1] * alpha;
            C[(size_t)(r0 + 8) * ldc + c0]     = acc[mt][nt][2] * alpha;
            C[(size_t)(r0 + 8) * ldc + c0 + 1] = acc[mt][nt][3] * alpha;
        }
}

// ---------------------------------------------------------------------------
// RoPE (GPT-J rotate_every_two), fp32 exp2f-based frequencies
// ---------------------------------------------------------------------------
__global__ void rope_kernel(float* __restrict__ Q, float* __restrict__ Km,
                            const int* __restrict__ pos)
{
    const int s = blockIdx.x;
    const float p = (float)pos[s];
    for (int idx = threadIdx.x; idx < H_NUM * (RD_DIM / 2); idx += blockDim.x) {
        int h = idx >> 5;
        int j = idx & 31;
        // 10000^(-2j/64) = 2^(-j * log2(10000)/32)
        float inv = exp2f(-0.41524101186092033f * (float)j);
        float ang = p * inv;
        float sn, cs;
        __sincosf(ang, &sn, &cs);
        size_t base = (size_t)s * E_DIM + (size_t)h * D_DIM + 2 * j;
        float q0 = Q[base], q1 = Q[base + 1];
        Q[base]     = q0 * cs - q1 * sn;
        Q[base + 1] = q1 * cs + q0 * sn;
        float k0 = Km[base], k1 = Km[base + 1];
        Km[base]     = k0 * cs - k1 * sn;
        Km[base + 1] = k1 * cs + k0 * sn;
    }
}

// ---------------------------------------------------------------------------
// Causal softmax; zero-fills only up to the 128-block edge (what PV reads).
// ---------------------------------------------------------------------------
__global__ void softmax_causal(float* __restrict__ P)
{
    const int m = blockIdx.x, h = blockIdx.y, tid = threadIdx.x;
    float* row = P + ((size_t)h * S_LEN + m) * S_LEN;
    const int nv = m + 1;
    const int nfill = ((m >> 7) + 1) << 7;
    __shared__ float sh[8];

    float mx = -3.4e38f;
    for (int n = tid; n < nv; n += 256) mx = fmaxf(mx, row[n]);
#pragma unroll
    for (int o = 16; o; o >>= 1) mx = fmaxf(mx, __shfl_xor_sync(0xffffffffu, mx, o));
    if ((tid & 31) == 0) sh[tid >> 5] = mx;
    __syncthreads();
    float bmax = sh[0];
#pragma unroll
    for (int w = 1; w < 8; w++) bmax = fmaxf(bmax, sh[w]);
    __syncthreads();

    float s = 0.f;
    for (int n = tid; n < nv; n += 256) {
        float e = __expf(row[n] - bmax);
        row[n] = e;
        s += e;
    }
#pragma unroll
    for (int o = 16; o; o >>= 1) s += __shfl_xor_sync(0xffffffffu, s, o);
    if ((tid & 31) == 0) sh[tid >> 5] = s;
    __syncthreads();
    float tot = 0.f;
#pragma unroll
    for (int w = 0; w < 8; w++) tot += sh[w];
    float inv = 1.f / tot;

    for (int n = tid; n < nfill; n += 256)
        row[n] = (n < nv) ? row[n] * inv : 0.f;
}

// ---------------------------------------------------------------------------
// Launch
// ---------------------------------------------------------------------------
extern "C" void kernel_launch(void* const* d_in, const int* in_sizes, int n_in,
                              void* d_out, int out_size)
{
    const float* hidden = (const float*)d_in[0];
    const float* wq     = (const float*)d_in[1];
    const float* wk     = (const float*)d_in[2];
    const float* wv     = (const float*)d_in[3];
    const float* wo     = (const float*)d_in[4];
    const int*   pos    = (const int*)d_in[5];
    float* out = (float*)d_out;

    float *Q, *K, *V, *ATT, *P;
    cudaGetSymbolAddress((void**)&Q,   g_Q);
    cudaGetSymbolAddress((void**)&K,   g_K);
    cudaGetSymbolAddress((void**)&V,   g_V);
    cudaGetSymbolAddress((void**)&ATT, g_ATT);
    cudaGetSymbolAddress((void**)&P,   g_P);

    cudaFuncSetAttribute(gemm_bf16x3<false, false, false>,
                         cudaFuncAttributeMaxDynamicSharedMemorySize, SMEM_BYTES);
    cudaFuncSetAttribute(gemm_bf16x3<true, true, false>,
                         cudaFuncAttributeMaxDynamicSharedMemorySize, SMEM_BYTES);
    cudaFuncSetAttribute(gemm_bf16x3<false, false, true>,
                         cudaFuncAttributeMaxDynamicSharedMemorySize, SMEM_BYTES);

    dim3 blk(256);

    // 1) Q/K/V projections
    dim3 gproj(E_DIM / BN, S_LEN / BM, 1);
    gemm_bf16x3<false, false, false><<<gproj, blk, SMEM_BYTES>>>(hidden, E_DIM, 0, wq, E_DIM, 0, Q, E_DIM, 0, E_DIM, 1.f);
    gemm_bf16x3<false, false, false><<<gproj, blk, SMEM_BYTES>>>(hidden, E_DIM, 0, wk, E_DIM, 0, K, E_DIM, 0, E_DIM, 1.f);
    gemm_bf16x3<false, false, false><<<gproj, blk, SMEM_BYTES>>>(hidden, E_DIM, 0, wv, E_DIM, 0, V, E_DIM, 0, E_DIM, 1.f);

    // 2) RoPE
    rope_kernel<<<S_LEN, 256>>>(Q, K, pos);

    // 3) scores[h] = (Q_h @ K_h^T) / 16, upper-tri blocks skipped
    dim3 gsc(S_LEN / BN, S_LEN / BM, H_NUM);
    gemm_bf16x3<true, true, false><<<gsc, blk, SMEM_BYTES>>>(
        Q, E_DIM, (size_t)D_DIM,
        K, E_DIM, (size_t)D_DIM,
        P, S_LEN, (size_t)S_LEN * S_LEN,
        D_DIM, 0.0625f);

    // 4) causal softmax
    softmax_causal<<<dim3(S_LEN, H_NUM), 256>>>(P);

    // 5) attn[h] = P_h @ V_h (K clamped causally)
    dim3 gav(D_DIM / BN, S_LEN / BM, H_NUM);
    gemm_bf16x3<false, false, true><<<gav, blk, SMEM_BYTES>>>(
        P, S_LEN, (size_t)S_LEN * S_LEN,
        V, E_DIM, (size_t)D_DIM,
        ATT, E_DIM, (size_t)D_DIM,
        S_LEN, 1.f);

    // 6) out = attn @ wo
    gemm_bf16x3<false, false, false><<<gproj, blk, SMEM_BYTES>>>(ATT, E_DIM, 0, wo, E_DIM, 0, out, E_DIM, 0, E_DIM, 1.f);
}

// round 3
// speedup vs baseline: 2.2779x; 1.0004x over previous
#include <cuda_runtime.h>
#include <cuda_bf16.h>
#include <cstdint>
#include <cstddef>

#define S_LEN 2048
#define E_DIM 4096
#define H_NUM 16
#define D_DIM 256
#define RD_DIM 64

// Scratch (device globals -- allocation inside kernel_launch is forbidden)
__device__ float g_Q[(size_t)S_LEN * E_DIM];
__device__ float g_K[(size_t)S_LEN * E_DIM];
__device__ float g_V[(size_t)S_LEN * E_DIM];
__device__ float g_ATT[(size_t)S_LEN * E_DIM];
__device__ float g_P[(size_t)H_NUM * S_LEN * S_LEN];

// ---------------------------------------------------------------------------
// bf16 split helpers: x = hi + lo, each bf16. Packs (x,y) pairs into one u32.
// ---------------------------------------------------------------------------
__device__ __forceinline__ uint32_t pack_split(float x, float y, uint32_t& lo) {
    __nv_bfloat162 h = __floats2bfloat162_rn(x, y);
    float rx = x - __bfloat162float(h.x);
    float ry = y - __bfloat162float(h.y);
    __nv_bfloat162 l = __floats2bfloat162_rn(rx, ry);
    lo = *reinterpret_cast<uint32_t*>(&l);
    return *reinterpret_cast<uint32_t*>(&h);
}

__device__ __forceinline__ void mma16(float c[4], const uint32_t a[4], const uint32_t b[2]) {
    asm volatile(
        "mma.sync.aligned.m16n8k16.row.col.f32.bf16.bf16.f32 "
        "{%0,%1,%2,%3},{%4,%5,%6,%7},{%8,%9},{%0,%1,%2,%3};\n"
        : "+f"(c[0]), "+f"(c[1]), "+f"(c[2]), "+f"(c[3])
        : "r"(a[0]), "r"(a[1]), "r"(a[2]), "r"(a[3]), "r"(b[0]), "r"(b[1]));
}

// ---------------------------------------------------------------------------
// 128x128x32 GEMM, C = alpha * A @ B, 3xBF16 emulation (hh + hl + lh).
// smem holds pre-split hi/lo bf16 pairs in fragment order; double-buffered.
// ---------------------------------------------------------------------------
#define BM 128
#define BN 128
#define BK 32
#define A_STR 20     // uint32 stride per A row (16 pairs + pad 4): conflict-free LDS
#define B_STR 136    // uint32 stride per B k2-row (128 + pad 8): conflict-free LDS
#define A_WORDS (128 * A_STR)
#define B_WORDS (16 * B_STR)
#define STG_WORDS (2 * A_WORDS + 2 * B_WORDS)   // AH, AL, BH, BL
#define SMEM_BYTES (2 * STG_WORDS * 4)

template<bool BTRANS, bool SKIP_UPPER, bool KLIMIT>
__global__ void __launch_bounds__(256, 1)
gemm_bf16x3(const float* __restrict__ A, int lda, size_t sA,
            const float* __restrict__ B, int ldb, size_t sB,
            float* __restrict__ C, int ldc, size_t sC,
            int K, float alpha)
{
    if (SKIP_UPPER && blockIdx.x > blockIdx.y) return;
    A += (size_t)blockIdx.z * sA;
    B += (size_t)blockIdx.z * sB;
    C += (size_t)blockIdx.z * sC;

    const int bm = blockIdx.y * BM;
    const int bn = blockIdx.x * BN;
    const int Keff = KLIMIT ? min(K, (int)(blockIdx.y + 1) * BM) : K;
    const int niter = Keff >> 5;

    extern __shared__ uint32_t sm[];

    const int tid  = threadIdx.x;
    const int lane = tid & 31;
    const int warp = tid >> 5;
    const int wm   = (warp >> 2) * 64;
    const int wn   = (warp & 3) * 32;
    const int lr   = lane >> 2;
    const int lc   = lane & 3;

    float acc[4][4][4];
#pragma unroll
    for (int i = 0; i < 4; i++)
#pragma unroll
        for (int j = 0; j < 4; j++)
#pragma unroll
            for (int r = 0; r < 4; r++) acc[i][j][r] = 0.f;

    float4 ra[4], rb[4];

    // ---- loaders (global -> regs) ----
    auto load_tiles = [&](int k0) {
#pragma unroll
        for (int i = 0; i < 4; i++) {
            int lin = tid + i * 256;
            int row = lin >> 3;
            int c4  = (lin & 7) * 4;
            ra[i] = *reinterpret_cast<const float4*>(A + (size_t)(bm + row) * lda + k0 + c4);
        }
        if (BTRANS) {
#pragma unroll
            for (int i = 0; i < 4; i++) {
                int lin = tid + i * 256;
                int n  = lin >> 3;
                int c4 = (lin & 7) * 4;
                rb[i] = *reinterpret_cast<const float4*>(B + (size_t)(bn + n) * ldb + k0 + c4);
            }
        } else {
#pragma unroll
            for (int i = 0; i < 2; i++) {
                int lin = tid + i * 256;
                int k2 = lin >> 5;
                int n0 = (lin & 31) * 4;
                rb[2 * i]     = *reinterpret_cast<const float4*>(B + (size_t)(k0 + 2 * k2)     * ldb + bn + n0);
                rb[2 * i + 1] = *reinterpret_cast<const float4*>(B + (size_t)(k0 + 2 * k2 + 1) * ldb + bn + n0);
            }
        }
    };

    // ---- split + store (regs -> smem stage) ----
    auto store_tiles = [&](int st) {
        uint32_t* AH = sm + st * STG_WORDS;
        uint32_t* AL = AH + A_WORDS;
        uint32_t* BH = AL + A_WORDS;
        uint32_t* BL = BH + B_WORDS;
#pragma unroll
        for (int i = 0; i < 4; i++) {
            int lin = tid + i * 256;
            int row = lin >> 3;
            int k2  = (lin & 7) * 2;
            uint32_t lo0, lo1;
            uint32_t hi0 = pack_split(ra[i].x, ra[i].y, lo0);
            uint32_t hi1 = pack_split(ra[i].z, ra[i].w, lo1);
            AH[row * A_STR + k2]     = hi0;
            AH[row * A_STR + k2 + 1] = hi1;
            AL[row * A_STR + k2]     = lo0;
            AL[row * A_STR + k2 + 1] = lo1;
        }
        if (BTRANS) {
#pragma unroll
            for (int i = 0; i < 4; i++) {
                int lin = tid + i * 256;
                int n  = lin >> 3;
                int k2 = (lin & 7) * 2;
                uint32_t lo0, lo1;
                uint32_t hi0 = pack_split(rb[i].x, rb[i].y, lo0);
                uint32_t hi1 = pack_split(rb[i].z, rb[i].w, lo1);
                BH[k2 * B_STR + n]       = hi0;
                BH[(k2 + 1) * B_STR + n] = hi1;
                BL[k2 * B_STR + n]       = lo0;
                BL[(k2 + 1) * B_STR + n] = lo1;
            }
        } else {
#pragma unroll
            for (int i = 0; i < 2; i++) {
                int lin = tid + i * 256;
                int k2 = lin >> 5;
                int n0 = (lin & 31) * 4;
                const float* f0 = reinterpret_cast<const float*>(&rb[2 * i]);
                const float* f1 = reinterpret_cast<const float*>(&rb[2 * i + 1]);
#pragma unroll
                for (int j = 0; j < 4; j++) {
                    uint32_t lo;
                    uint32_t hi = pack_split(f0[j], f1[j], lo);
                    BH[k2 * B_STR + n0 + j] = hi;
                    BL[k2 * B_STR + n0 + j] = lo;
                }
            }
        }
    };

    // ---- pipeline ----
    load_tiles(0);
    store_tiles(0);
    __syncthreads();

    for (int it = 0; it < niter; ++it) {
        if (it + 1 < niter) load_tiles((it + 1) << 5);

        const int st = it & 1;
        const uint32_t* AH = sm + st * STG_WORDS;
        const uint32_t* AL = AH + A_WORDS;
        const uint32_t* BH = AL + A_WORDS;
        const uint32_t* BL = BH + B_WORDS;

#pragma unroll
        for (int ks2 = 0; ks2 < 16; ks2 += 8) {
            uint32_t ah[4][4], al[4][4], bh[4][2], bl[4][2];
#pragma unroll
            for (int mt = 0; mt < 4; mt++) {
                int r0 = wm + mt * 16 + lr;
                ah[mt][0] = AH[r0 * A_STR + ks2 + lc];
                ah[mt][1] = AH[(r0 + 8) * A_STR + ks2 + lc];
                ah[mt][2] = AH[r0 * A_STR + ks2 + lc + 4];
                ah[mt][3] = AH[(r0 + 8) * A_STR + ks2 + lc + 4];
                al[mt][0] = AL[r0 * A_STR + ks2 + lc];
                al[mt][1] = AL[(r0 + 8) * A_STR + ks2 + lc];
                al[mt][2] = AL[r0 * A_STR + ks2 + lc + 4];
                al[mt][3] = AL[(r0 + 8) * A_STR + ks2 + lc + 4];
            }
#pragma unroll
            for (int nt = 0; nt < 4; nt++) {
                int n = wn + nt * 8 + lr;
                bh[nt][0] = BH[(ks2 + lc) * B_STR + n];
                bh[nt][1] = BH[(ks2 + lc + 4) * B_STR + n];
                bl[nt][0] = BL[(ks2 + lc) * B_STR + n];
                bl[nt][1] = BL[(ks2 + lc + 4) * B_STR + n];
            }
#pragma unroll
            for (int mt = 0; mt < 4; mt++)
#pragma unroll
                for (int nt = 0; nt < 4; nt++) {
                    mma16(acc[mt][nt], ah[mt], bh[nt]);   // hi*hi
                    mma16(acc[mt][nt], ah[mt], bl[nt]);   // hi*lo
                    mma16(acc[mt][nt], al[mt], bh[nt]);   // lo*hi
                }
        }

        if (it + 1 < niter) store_tiles((it + 1) & 1);
        __syncthreads();
    }

    // ---- epilogue ----
#pragma unroll
    for (int mt = 0; mt < 4; mt++)
#pragma unroll
        for (int nt = 0; nt < 4; nt++) {
            int r0 = bm + wm + mt * 16 + lr;
            int c0 = bn + wn + nt * 8 + lc * 2;
            C[(size_t)r0 * ldc + c0]           = acc[mt][nt][0] * alpha;
            C[(size_t)r0 * ldc + c0 + 1]       = acc[mt][nt][1] * alpha;
            C[(size_t)(r0 + 8) * ldc + c0]     = acc[mt][nt][2] * alpha;
            C[(size_t)(r0 + 8) * ldc + c0 + 1] = acc[mt][nt][3] * alpha;
        }
}

// ---------------------------------------------------------------------------
// RoPE (GPT-J rotate_every_two), fp32 exp2f-based frequencies
// ---------------------------------------------------------------------------
__global__ void rope_kernel(float* __restrict__ Q, float* __restrict__ Km,
                            const int* __restrict__ pos)
{
    const int s = blockIdx.x;
    const float p = (float)pos[s];
    for (int idx = threadIdx.x; idx < H_NUM * (RD_DIM / 2); idx += blockDim.x) {
        int h = idx >> 5;
        int j = idx & 31;
        // 10000^(-2j/64) = 2^(-j * log2(10000)/32)
        float inv = exp2f(-0.41524101186092033f * (float)j);
        float ang = p * inv;
        float sn, cs;
        __sincosf(ang, &sn, &cs);
        size_t base = (size_t)s * E_DIM + (size_t)h * D_DIM + 2 * j;
        float q0 = Q[base], q1 = Q[base + 1];
        Q[base]     = q0 * cs - q1 * sn;
        Q[base + 1] = q1 * cs + q0 * sn;
        float k0 = Km[base], k1 = Km[base + 1];
        Km[base]     = k0 * cs - k1 * sn;
        Km[base + 1] = k1 * cs + k0 * sn;
    }
}

// ---------------------------------------------------------------------------
// Causal softmax; zero-fills only up to the 128-block edge (what PV reads).
// ---------------------------------------------------------------------------
__global__ void softmax_causal(float* __restrict__ P)
{
    const int m = blockIdx.x, h = blockIdx.y, tid = threadIdx.x;
    float* row = P + ((size_t)h * S_LEN + m) * S_LEN;
    const int nv = m + 1;
    const int nfill = ((m >> 7) + 1) << 7;
    __shared__ float sh[8];

    float mx = -3.4e38f;
    for (int n = tid; n < nv; n += 256) mx = fmaxf(mx, row[n]);
#pragma unroll
    for (int o = 16; o; o >>= 1) mx = fmaxf(mx, __shfl_xor_sync(0xffffffffu, mx, o));
    if ((tid & 31) == 0) sh[tid >> 5] = mx;
    __syncthreads();
    float bmax = sh[0];
#pragma unroll
    for (int w = 1; w < 8; w++) bmax = fmaxf(bmax, sh[w]);
    __syncthreads();

    float s = 0.f;
    for (int n = tid; n < nv; n += 256) {
        float e = __expf(row[n] - bmax);
        row[n] = e;
        s += e;
    }
#pragma unroll
    for (int o = 16; o; o >>= 1) s += __shfl_xor_sync(0xffffffffu, s, o);
    if ((tid & 31) == 0) sh[tid >> 5] = s;
    __syncthreads();
    float tot = 0.f;
#pragma unroll
    for (int w = 0; w < 8; w++) tot += sh[w];
    float inv = 1.f / tot;

    for (int n = tid; n < nfill; n += 256)
        row[n] = (n < nv) ? row[n] * inv : 0.f;
}

// ---------------------------------------------------------------------------
// Launch
// ---------------------------------------------------------------------------
extern "C" void kernel_launch(void* const* d_in, const int* in_sizes, int n_in,
                              void* d_out, int out_size)
{
    const float* hidden = (const float*)d_in[0];
    const float* wq     = (const float*)d_in[1];
    const float* wk     = (const float*)d_in[2];
    const float* wv     = (const float*)d_in[3];
    const float* wo     = (const float*)d_in[4];
    const int*   pos    = (const int*)d_in[5];
    float* out = (float*)d_out;

    float *Q, *K, *V, *ATT, *P;
    cudaGetSymbolAddress((void**)&Q,   g_Q);
    cudaGetSymbolAddress((void**)&K,   g_K);
    cudaGetSymbolAddress((void**)&V,   g_V);
    cudaGetSymbolAddress((void**)&ATT, g_ATT);
    cudaGetSymbolAddress((void**)&P,   g_P);

    cudaFuncSetAttribute(gemm_bf16x3<false, false, false>,
                         cudaFuncAttributeMaxDynamicSharedMemorySize, SMEM_BYTES);
    cudaFuncSetAttribute(gemm_bf16x3<true, true, false>,
                         cudaFuncAttributeMaxDynamicSharedMemorySize, SMEM_BYTES);
    cudaFuncSetAttribute(gemm_bf16x3<false, false, true>,
                         cudaFuncAttributeMaxDynamicSharedMemorySize, SMEM_BYTES);

    dim3 blk(256);

    // 1) Q/K/V projections
    dim3 gproj(E_DIM / BN, S_LEN / BM, 1);
    gemm_bf16x3<false, false, false><<<gproj, blk, SMEM_BYTES>>>(hidden, E_DIM, 0, wq, E_DIM, 0, Q, E_DIM, 0, E_DIM, 1.f);
    gemm_bf16x3<false, false, false><<<gproj, blk, SMEM_BYTES>>>(hidden, E_DIM, 0, wk, E_DIM, 0, K, E_DIM, 0, E_DIM, 1.f);
    gemm_bf16x3<false, false, false><<<gproj, blk, SMEM_BYTES>>>(hidden, E_DIM, 0, wv, E_DIM, 0, V, E_DIM, 0, E_DIM, 1.f);

    // 2) RoPE
    rope_kernel<<<S_LEN, 256>>>(Q, K, pos);

    // 3) scores[h] = (Q_h @ K_h^T) / 16, upper-tri blocks skipped
    dim3 gsc(S_LEN / BN, S_LEN / BM, H_NUM);
    gemm_bf16x3<true, true, false><<<gsc, blk, SMEM_BYTES>>>(
        Q, E_DIM, (size_t)D_DIM,
        K, E_DIM, (size_t)D_DIM,
        P, S_LEN, (size_t)S_LEN * S_LEN,
        D_DIM, 0.0625f);

    // 4) causal softmax
    softmax_causal<<<dim3(S_LEN, H_NUM), 256>>>(P);

    // 5) attn[h] = P_h @ V_h (K clamped causally)
    dim3 gav(D_DIM / BN, S_LEN / BM, H_NUM);
    gemm_bf16x3<false, false, true><<<gav, blk, SMEM_BYTES>>>(
        P, S_LEN, (size_t)S_LEN * S_LEN,
        V, E_DIM, (size_t)D_DIM,
        ATT, E_DIM, (size_t)D_DIM,
        S_LEN, 1.f);

    // 6) out = attn @ wo
    gemm_bf16x3<false, false, false><<<gproj, blk, SMEM_BYTES>>>(ATT, E_DIM, 0, wo, E_DIM, 0, out, E_DIM, 0, E_DIM, 1.f);
}